// round 1
// baseline (speedup 1.0000x reference)
#include <cuda_runtime.h>
#include <cuda_bf16.h>

#define TPB 256

__global__ __launch_bounds__(TPB) void gaussians_cov_kernel(
    const float4* __restrict__ quat,   // [n] as float4 (r,x,y,z)
    const float*  __restrict__ scales, // [n*3]
    float*        __restrict__ out,    // [n*9]
    int n)
{
    __shared__ float ss[3 * TPB];   // staged scales, flat coalesced order
    __shared__ float so[9 * TPB];   // staged output, row-major per gaussian

    const int tid  = threadIdx.x;
    const int base = blockIdx.x * TPB;
    const int i    = base + tid;

    // ---- coalesced load of this block's scales into smem ----
    #pragma unroll
    for (int k = 0; k < 3; k++) {
        int idx = tid + k * TPB;
        long long g = (long long)base * 3 + idx;
        ss[idx] = (g < (long long)n * 3) ? scales[g] : 0.0f;
    }
    __syncthreads();

    if (i < n) {
        // quaternion: clean float4 load
        float4 qv = quat[i];
        float r = qv.x, x = qv.y, y = qv.z, z = qv.w;

        float n2  = r*r + x*x + y*y + z*z;
        float inv = rsqrtf(fmaxf(n2, 1e-24f));   // == 1/max(||q||,1e-12)
        r *= inv; x *= inv; y *= inv; z *= inv;

        // rotation matrix (row-major)
        float R00 = 1.0f - 2.0f*(y*y + z*z);
        float R01 = 2.0f*(x*y - r*z);
        float R02 = 2.0f*(x*z + r*y);
        float R10 = 2.0f*(x*y + r*z);
        float R11 = 1.0f - 2.0f*(x*x + z*z);
        float R12 = 2.0f*(y*z - r*x);
        float R20 = 2.0f*(x*z - r*y);
        float R21 = 2.0f*(y*z + r*x);
        float R22 = 1.0f - 2.0f*(x*x + y*y);

        // per-thread scales from smem (stride-3 LDS: conflict-free, gcd(3,32)=1)
        float s0 = ss[tid*3 + 0];
        float s1 = ss[tid*3 + 1];
        float s2 = ss[tid*3 + 2];
        float t0 = s0*s0, t1 = s1*s1, t2 = s2*s2;

        // cov = R * diag(s^2) * R^T  (full 3x3, matches reference output)
        float* o = &so[tid * 9];   // stride-9 STS: conflict-free, gcd(9,32)=1
        o[0] = R00*R00*t0 + R01*R01*t1 + R02*R02*t2;
        o[1] = R00*R10*t0 + R01*R11*t1 + R02*R12*t2;
        o[2] = R00*R20*t0 + R01*R21*t1 + R02*R22*t2;
        o[3] = R10*R00*t0 + R11*R01*t1 + R12*R02*t2;
        o[4] = R10*R10*t0 + R11*R11*t1 + R12*R12*t2;
        o[5] = R10*R20*t0 + R11*R21*t1 + R12*R22*t2;
        o[6] = R20*R00*t0 + R21*R01*t1 + R22*R02*t2;
        o[7] = R20*R10*t0 + R21*R11*t1 + R22*R12*t2;
        o[8] = R20*R20*t0 + R21*R21*t1 + R22*R22*t2;
    }
    __syncthreads();

    // ---- coalesced writeback ----
    if (base + TPB <= n) {
        // full block: 9216-byte region, base offset 9216*bid is 16B-aligned
        float4*       out4 = reinterpret_cast<float4*>(out + (size_t)base * 9);
        const float4* so4  = reinterpret_cast<const float4*>(so);
        #pragma unroll
        for (int k = tid; k < (9 * TPB) / 4; k += TPB)
            out4[k] = so4[k];
    } else {
        int cnt = n - base;                 // tail block
        for (int k = tid; k < cnt * 9; k += TPB)
            out[(size_t)base * 9 + k] = so[k];
    }
}

extern "C" void kernel_launch(void* const* d_in, const int* in_sizes, int n_in,
                              void* d_out, int out_size) {
    const float4* quat   = (const float4*)d_in[0];   // quaternions [n,4]
    const float*  scales = (const float*)d_in[1];    // scales [n,3]
    float*        out    = (float*)d_out;            // covariance [n,3,3]
    int n = in_sizes[0] / 4;

    int blocks = (n + TPB - 1) / TPB;
    gaussians_cov_kernel<<<blocks, TPB>>>(quat, scales, out, n);
}

// round 2
// speedup vs baseline: 1.0054x; 1.0054x over previous
#include <cuda_runtime.h>
#include <cuda_bf16.h>

#define TPB 256
#define G   2            // gaussians per thread
#define BPB (TPB * G)    // gaussians per block = 512

__device__ __forceinline__ void cov_from_q(float4 qv, float s0, float s1, float s2,
                                           float* __restrict__ o /* stride-1, 9 floats */)
{
    float r = qv.x, x = qv.y, y = qv.z, z = qv.w;
    float n2  = r*r + x*x + y*y + z*z;
    float inv = rsqrtf(fmaxf(n2, 1e-24f));   // == 1/max(||q||,1e-12)
    r *= inv; x *= inv; y *= inv; z *= inv;

    float R00 = 1.0f - 2.0f*(y*y + z*z);
    float R01 = 2.0f*(x*y - r*z);
    float R02 = 2.0f*(x*z + r*y);
    float R10 = 2.0f*(x*y + r*z);
    float R11 = 1.0f - 2.0f*(x*x + z*z);
    float R12 = 2.0f*(y*z - r*x);
    float R20 = 2.0f*(x*z - r*y);
    float R21 = 2.0f*(y*z + r*x);
    float R22 = 1.0f - 2.0f*(x*x + y*y);

    float t0 = s0*s0, t1 = s1*s1, t2 = s2*s2;

    float c01 = R00*R10*t0 + R01*R11*t1 + R02*R12*t2;
    float c02 = R00*R20*t0 + R01*R21*t1 + R02*R22*t2;
    float c12 = R10*R20*t0 + R11*R21*t1 + R12*R22*t2;
    o[0] = R00*R00*t0 + R01*R01*t1 + R02*R02*t2;
    o[1] = c01;
    o[2] = c02;
    o[3] = c01;
    o[4] = R10*R10*t0 + R11*R11*t1 + R12*R12*t2;
    o[5] = c12;
    o[6] = c02;
    o[7] = c12;
    o[8] = R20*R20*t0 + R21*R21*t1 + R22*R22*t2;
}

__global__ __launch_bounds__(TPB) void gaussians_cov_kernel(
    const float4* __restrict__ quat,   // [n] as float4 (r,x,y,z)
    const float*  __restrict__ scales, // [n*3]
    float*        __restrict__ out,    // [n*9]
    int n)
{
    __shared__ float ss[3 * BPB];   // staged scales (6 KB)
    __shared__ float so[9 * BPB];   // staged output (18 KB)

    const int tid  = threadIdx.x;
    const int base = blockIdx.x * BPB;

    // ---- coalesced load of this block's scales into smem ----
    #pragma unroll
    for (int k = 0; k < 3 * G; k++) {
        int idx = tid + k * TPB;
        long long g = (long long)base * 3 + idx;
        ss[idx] = (g < (long long)n * 3) ? scales[g] : 0.0f;
    }
    __syncthreads();

    // ---- issue both quat loads up front (2x MLP), then compute ----
    const int i0 = base + tid;
    const int i1 = base + TPB + tid;

    float4 q0, q1;
    if (i0 < n) q0 = quat[i0];
    if (i1 < n) q1 = quat[i1];

    if (i0 < n) {
        cov_from_q(q0, ss[tid*3+0], ss[tid*3+1], ss[tid*3+2], &so[tid * 9]);
    }
    if (i1 < n) {
        int t = TPB + tid;
        cov_from_q(q1, ss[t*3+0], ss[t*3+1], ss[t*3+2], &so[t * 9]);
    }
    __syncthreads();

    // ---- coalesced writeback ----
    if (base + BPB <= n) {
        float4*       out4 = reinterpret_cast<float4*>(out + (size_t)base * 9);
        const float4* so4  = reinterpret_cast<const float4*>(so);
        #pragma unroll
        for (int kk = 0; kk < (9 * BPB / 4 + TPB - 1) / TPB; kk++) {
            int k = tid + kk * TPB;
            if (k < 9 * BPB / 4) out4[k] = so4[k];
        }
    } else {
        int cnt = n - base;                 // tail block
        if (cnt > 0)
            for (int k = tid; k < cnt * 9; k += TPB)
                out[(size_t)base * 9 + k] = so[k];
    }
}

extern "C" void kernel_launch(void* const* d_in, const int* in_sizes, int n_in,
                              void* d_out, int out_size) {
    const float4* quat   = (const float4*)d_in[0];   // quaternions [n,4]
    const float*  scales = (const float*)d_in[1];    // scales [n,3]
    float*        out    = (float*)d_out;            // covariance [n,3,3]
    int n = in_sizes[0] / 4;

    int blocks = (n + BPB - 1) / BPB;
    gaussians_cov_kernel<<<blocks, TPB>>>(quat, scales, out, n);
}

// round 3
// speedup vs baseline: 1.1352x; 1.1291x over previous
#include <cuda_runtime.h>
#include <cuda_bf16.h>

#define TPB 256
#define WPB (TPB / 32)      // warps per block = 8
#define GPW 128             // gaussians per warp
#define GPB (WPB * GPW)     // gaussians per block = 1024

__device__ __forceinline__ void cov_from_q(float4 qv, float s0, float s1, float s2,
                                           float* __restrict__ o /* 9 floats */)
{
    float r = qv.x, x = qv.y, y = qv.z, z = qv.w;
    float n2  = r*r + x*x + y*y + z*z;
    float inv = rsqrtf(fmaxf(n2, 1e-24f));   // == 1/max(||q||,1e-12)
    r *= inv; x *= inv; y *= inv; z *= inv;

    float R00 = 1.0f - 2.0f*(y*y + z*z);
    float R01 = 2.0f*(x*y - r*z);
    float R02 = 2.0f*(x*z + r*y);
    float R10 = 2.0f*(x*y + r*z);
    float R11 = 1.0f - 2.0f*(x*x + z*z);
    float R12 = 2.0f*(y*z - r*x);
    float R20 = 2.0f*(x*z - r*y);
    float R21 = 2.0f*(y*z + r*x);
    float R22 = 1.0f - 2.0f*(x*x + y*y);

    float t0 = s0*s0, t1 = s1*s1, t2 = s2*s2;

    float c01 = R00*R10*t0 + R01*R11*t1 + R02*R12*t2;
    float c02 = R00*R20*t0 + R01*R21*t1 + R02*R22*t2;
    float c12 = R10*R20*t0 + R11*R21*t1 + R12*R22*t2;
    o[0] = R00*R00*t0 + R01*R01*t1 + R02*R02*t2;
    o[1] = c01;
    o[2] = c02;
    o[3] = c01;
    o[4] = R10*R10*t0 + R11*R11*t1 + R12*R12*t2;
    o[5] = c12;
    o[6] = c02;
    o[7] = c12;
    o[8] = R20*R20*t0 + R21*R21*t1 + R22*R22*t2;
}

__global__ __launch_bounds__(TPB, 4) void gaussians_cov_kernel(
    const float4* __restrict__ quat,   // [n] as float4 (r,x,y,z)
    const float*  __restrict__ scales, // [n*3]
    float*        __restrict__ out,    // [n*9]
    int n)
{
    // warp-private smem slices: no block-wide barriers anywhere
    __shared__ float ss[WPB * 3 * GPW];   // 12 KB: staged scales
    __shared__ float so[WPB * 9 * GPW];   // 36 KB: staged output

    const int wid      = threadIdx.x >> 5;
    const int lane     = threadIdx.x & 31;
    const int warpBase = blockIdx.x * GPB + wid * GPW;

    float* wss = ss + wid * (3 * GPW);
    float* wso = so + wid * (9 * GPW);

    if (warpBase + GPW <= n) {
        // ---- front-batch ALL global loads (16 per lane in flight) ----
        float sv[12];
        const float* sp = scales + (size_t)warpBase * 3;
        #pragma unroll
        for (int k = 0; k < 12; k++)
            sv[k] = sp[k * 32 + lane];                // coalesced

        float4 q[4];
        #pragma unroll
        for (int j = 0; j < 4; j++)
            q[j] = quat[warpBase + j * 32 + lane];    // LDG.128 x4

        // stage scales to warp-private smem
        #pragma unroll
        for (int k = 0; k < 12; k++)
            wss[k * 32 + lane] = sv[k];
        __syncwarp();

        // compute 4 covariances (stride-3 LDS + stride-9 STS, conflict-free)
        #pragma unroll
        for (int j = 0; j < 4; j++) {
            int t = j * 32 + lane;
            cov_from_q(q[j], wss[t*3+0], wss[t*3+1], wss[t*3+2], &wso[t * 9]);
        }
        __syncwarp();

        // ---- coalesced writeback: exactly 9 float4 per lane ----
        float4*       o4 = reinterpret_cast<float4*>(out + (size_t)warpBase * 9);
        const float4* s4 = reinterpret_cast<const float4*>(wso);
        #pragma unroll
        for (int k = 0; k < 9; k++)
            o4[k * 32 + lane] = s4[k * 32 + lane];
    } else {
        // ---- tail: guarded scalar path (at most one partial warp matters) ----
        for (int g = warpBase + lane; g < n; g += 32) {
            float4 qv = quat[g];
            float  oo[9];
            cov_from_q(qv, scales[(size_t)g*3+0], scales[(size_t)g*3+1],
                           scales[(size_t)g*3+2], oo);
            #pragma unroll
            for (int k = 0; k < 9; k++)
                out[(size_t)g * 9 + k] = oo[k];
        }
    }
}

extern "C" void kernel_launch(void* const* d_in, const int* in_sizes, int n_in,
                              void* d_out, int out_size) {
    const float4* quat   = (const float4*)d_in[0];   // quaternions [n,4]
    const float*  scales = (const float*)d_in[1];    // scales [n,3]
    float*        out    = (float*)d_out;            // covariance [n,3,3]
    int n = in_sizes[0] / 4;

    int blocks = (n + GPB - 1) / GPB;
    gaussians_cov_kernel<<<blocks, TPB>>>(quat, scales, out, n);
}